// round 7
// baseline (speedup 1.0000x reference)
#include <cuda_runtime.h>
#include <cstdint>

#define N_NODES 50000
#define N_EDGES 800000
#define DIM 128
#define DIM4 32
#define AS 132      // A smem stride (floats)
#define WS 136      // W smem stride (floats)
#define TM 128      // gemm tile rows
#define GEMM_T 512  // gemm threads

// Scratch (allocation-free: __device__ globals)
__device__ float g_h[N_NODES * DIM];    // layer-1 gemm output (gather source L1)
__device__ float g_z[N_NODES * DIM];    // layer-1 activations (gemm2 input)
__device__ float g_h2[N_NODES * DIM];   // layer-2 gemm output (gather source L2)
__device__ float g_deg[N_NODES];
__device__ float g_dinv[N_NODES];
__device__ int   g_cnt[N_NODES];
__device__ int   g_cursor[N_NODES];
__device__ int   g_rowstart[N_NODES + 1];
__device__ int   g_blocksums[128];
__device__ int2  g_edges[N_EDGES];

// ---------------------------------------------------------------------------
__global__ void k_init(int n) {
    int i = blockIdx.x * blockDim.x + threadIdx.x;
    if (i < n) { g_deg[i] = 1.0f; g_cnt[i] = 0; g_cursor[i] = 0; }
}

__global__ void k_count(const int* __restrict__ dst, const float* __restrict__ ew, int e) {
    int i = blockIdx.x * blockDim.x + threadIdx.x;
    if (i < e) {
        int d = dst[i];
        atomicAdd(&g_deg[d], ew[i]);
        atomicAdd(&g_cnt[d], 1);
    }
}

// ---------------------------------------------------------------------------
__device__ __forceinline__ int warp_incl_scan(int x, int lane) {
    #pragma unroll
    for (int o = 1; o < 32; o <<= 1) {
        int y = __shfl_up_sync(0xffffffffu, x, o);
        if (lane >= o) x += y;
    }
    return x;
}

// scan phase 1 (+ fused dinv)
__global__ void k_scan1(int n) {
    __shared__ int warpsums[32];
    const int lane = threadIdx.x & 31;
    const int warp = threadIdx.x >> 5;
    int i = blockIdx.x * 1024 + threadIdx.x;
    if (i < n) g_dinv[i] = rsqrtf(g_deg[i]);
    int v = (i < n) ? g_cnt[i] : 0;
    int x = warp_incl_scan(v, lane);
    if (lane == 31) warpsums[warp] = x;
    __syncthreads();
    if (threadIdx.x < 32) {
        int s = warpsums[threadIdx.x];
        int xs = warp_incl_scan(s, threadIdx.x);
        warpsums[threadIdx.x] = xs - s;
    }
    __syncthreads();
    int excl = (x - v) + warpsums[warp];
    if (i < n) g_rowstart[i] = excl;
    if (threadIdx.x == 1023) g_blocksums[blockIdx.x] = excl + v;
}

__global__ void k_scan2(int nblocks, int n, int e) {
    __shared__ int tmp[128];
    const int lane = threadIdx.x & 31;
    if (threadIdx.x < 128) tmp[threadIdx.x] = (threadIdx.x < nblocks) ? g_blocksums[threadIdx.x] : 0;
    __syncthreads();
    if (threadIdx.x < 32) {
        int carry = 0;
        for (int c = 0; c < 128; c += 32) {
            int v = tmp[c + lane];
            int x = warp_incl_scan(v, lane);
            tmp[c + lane] = (x - v) + carry;
            carry += __shfl_sync(0xffffffffu, x, 31);
        }
    }
    __syncthreads();
    if (threadIdx.x < 128 && threadIdx.x < nblocks) g_blocksums[threadIdx.x] = tmp[threadIdx.x];
    if (threadIdx.x == 0) g_rowstart[n] = e;
}

__global__ void k_scan3(int n) {
    int i = blockIdx.x * blockDim.x + threadIdx.x;
    if (i < n) g_rowstart[i] += g_blocksums[i >> 10];
}

__global__ void k_reorder(const int* __restrict__ src, const int* __restrict__ dst,
                          const float* __restrict__ ew, int e) {
    int i = blockIdx.x * blockDim.x + threadIdx.x;
    if (i < e) {
        int s = src[i];
        int d = dst[i];
        float nrm = g_dinv[s] * ew[i] * g_dinv[d];
        int p = g_rowstart[d] + atomicAdd(&g_cursor[d], 1);
        g_edges[p] = make_int2(s, __float_as_int(nrm));
    }
}

// ---------------------------------------------------------------------------
// tf32 tensor GEMM v3: 512 thr / 16 warps (8m x 2n), warp tile 16x64.
// Persistent, cp.async double-buffered A, 128x128 block tile.
// ---------------------------------------------------------------------------
__device__ __forceinline__ uint32_t f2tf32(float v) {
    uint32_t o;
    asm("cvt.rna.tf32.f32 %0, %1;" : "=r"(o) : "f"(v));
    return o;
}

__device__ __forceinline__ void mma_tf32(float* c, const uint32_t* a,
                                         uint32_t b0, uint32_t b1) {
    asm volatile(
        "mma.sync.aligned.m16n8k8.row.col.f32.tf32.tf32.f32 "
        "{%0,%1,%2,%3}, {%4,%5,%6,%7}, {%8,%9}, {%0,%1,%2,%3};"
        : "+f"(c[0]), "+f"(c[1]), "+f"(c[2]), "+f"(c[3])
        : "r"(a[0]), "r"(a[1]), "r"(a[2]), "r"(a[3]), "r"(b0), "r"(b1));
}

__device__ __forceinline__ void load_tileA(float* dst, const float* __restrict__ in,
                                           int t, int n, int tid) {
    int row0 = t * TM;
    #pragma unroll 2
    for (int i = tid; i < TM * 32; i += GEMM_T) {
        int r = i >> 5, c = (i & 31) << 2;
        float* d = dst + r * AS + c;
        if (row0 + r < n) {
            uint32_t s = (uint32_t)__cvta_generic_to_shared(d);
            asm volatile("cp.async.cg.shared.global [%0], [%1], 16;"
                         :: "r"(s), "l"(in + (size_t)(row0 + r) * DIM + c));
        } else {
            *(float4*)d = make_float4(0.f, 0.f, 0.f, 0.f);
        }
    }
}

__global__ void __launch_bounds__(GEMM_T, 1)
k_gemm(const float* __restrict__ in, const float* __restrict__ W,
       float* __restrict__ out, int n) {
    extern __shared__ uint32_t smem[];
    uint32_t* Ws = smem;                                  // [128][WS] tf32
    float* As0 = (float*)(smem + DIM * WS);               // [128][AS] fp32
    float* As1 = As0 + TM * AS;

    const int tid  = threadIdx.x;
    const int lane = tid & 31;
    const int warp = tid >> 5;
    const int warp_m = (warp & 7) * 16;
    const int warp_n = (warp >> 3) * 64;
    const int ntiles = (n + TM - 1) / TM;

    // stage W -> tf32 smem
    for (int i = tid; i < DIM * DIM4; i += GEMM_T) {
        int k = i >> 5, c4 = (i & 31) << 2;
        float4 v = ((const float4*)W)[i];
        uint32_t* p = Ws + k * WS + c4;
        p[0] = f2tf32(v.x); p[1] = f2tf32(v.y); p[2] = f2tf32(v.z); p[3] = f2tf32(v.w);
    }

    int t = blockIdx.x;
    if (t < ntiles) {
        load_tileA(As0, in, t, n, tid);
        asm volatile("cp.async.commit_group;");
    }

    int buf = 0;
    const int ar  = lane >> 2;
    const int akc = lane & 3;

    for (; t < ntiles; t += gridDim.x) {
        int tn = t + gridDim.x;
        if (tn < ntiles) {
            load_tileA(buf ? As0 : As1, in, tn, n, tid);
            asm volatile("cp.async.commit_group;");
            asm volatile("cp.async.wait_group 1;");
        } else {
            asm volatile("cp.async.wait_group 0;");
        }
        __syncthreads();   // also covers W staging on first iteration

        const float* A = buf ? As1 : As0;
        float acc[8][4];
        #pragma unroll
        for (int nt = 0; nt < 8; nt++)
            #pragma unroll
            for (int q = 0; q < 4; q++) acc[nt][q] = 0.0f;

        #pragma unroll
        for (int ks = 0; ks < 16; ks++) {
            const int k0 = ks * 8;
            uint32_t a[4];
            {
                int r = warp_m + ar;
                a[0] = f2tf32(A[r * AS + k0 + akc]);
                a[1] = f2tf32(A[(r + 8) * AS + k0 + akc]);
                a[2] = f2tf32(A[r * AS + k0 + akc + 4]);
                a[3] = f2tf32(A[(r + 8) * AS + k0 + akc + 4]);
            }
            #pragma unroll
            for (int nt = 0; nt < 8; nt++) {
                int bn = warp_n + nt * 8 + (lane >> 2);
                int bk = k0 + (lane & 3);
                uint32_t b0 = Ws[bk * WS + bn];
                uint32_t b1 = Ws[(bk + 4) * WS + bn];
                mma_tf32(acc[nt], a, b0, b1);
            }
        }

        int row0 = t * TM;
        int rbase = row0 + warp_m + (lane >> 2);
        #pragma unroll
        for (int nt = 0; nt < 8; nt++) {
            int col = warp_n + nt * 8 + 2 * (lane & 3);
            if (rbase < n)
                *(float2*)(out + (size_t)rbase * DIM + col) =
                    make_float2(acc[nt][0], acc[nt][1]);
            if (rbase + 8 < n)
                *(float2*)(out + (size_t)(rbase + 8) * DIM + col) =
                    make_float2(acc[nt][2], acc[nt][3]);
        }
        __syncthreads();   // tile buffer free for next prefetch
        buf ^= 1;
    }
}

// ---------------------------------------------------------------------------
// Gather-aggregate (no atomics), node range [node0, node1).
// Unroll 8: 8 independent LDG.128 per lane in flight.
// ---------------------------------------------------------------------------
__global__ void k_agg(const float* __restrict__ h, const float* __restrict__ b,
                      float* __restrict__ out, int node0, int node1) {
    int t = blockIdx.x * blockDim.x + threadIdx.x;
    int node = node0 + (t >> 5);
    int lane = t & 31;
    if (node >= node1) return;

    int beg = g_rowstart[node];
    int end = g_rowstart[node + 1];

    float di = g_dinv[node];
    float sl = di * di;
    float4 hv = ((const float4*)(h + (size_t)node * DIM))[lane];
    float4 acc = make_float4(hv.x * sl, hv.y * sl, hv.z * sl, hv.w * sl);

    for (int j0 = beg; j0 < end; j0 += 32) {
        int m = end - j0; if (m > 32) m = 32;
        int2 ed = make_int2(0, 0);
        if (lane < m) ed = g_edges[j0 + lane];

        int k = 0;
        for (; k + 8 <= m; k += 8) {
            int s[8]; float nr[8];
            #pragma unroll
            for (int q = 0; q < 8; q++) {
                s[q]  = __shfl_sync(0xffffffffu, ed.x, k + q);
                nr[q] = __int_as_float(__shfl_sync(0xffffffffu, ed.y, k + q));
            }
            float4 v[8];
            #pragma unroll
            for (int q = 0; q < 8; q++)
                v[q] = ((const float4*)(h + (size_t)s[q] * DIM))[lane];
            #pragma unroll
            for (int q = 0; q < 8; q++) {
                acc.x = fmaf(nr[q], v[q].x, acc.x);
                acc.y = fmaf(nr[q], v[q].y, acc.y);
                acc.z = fmaf(nr[q], v[q].z, acc.z);
                acc.w = fmaf(nr[q], v[q].w, acc.w);
            }
        }
        for (; k < m; k++) {
            int   s0 = __shfl_sync(0xffffffffu, ed.x, k);
            float n0 = __int_as_float(__shfl_sync(0xffffffffu, ed.y, k));
            float4 v0 = ((const float4*)(h + (size_t)s0 * DIM))[lane];
            acc.x = fmaf(n0, v0.x, acc.x); acc.y = fmaf(n0, v0.y, acc.y);
            acc.z = fmaf(n0, v0.z, acc.z); acc.w = fmaf(n0, v0.w, acc.w);
        }
    }

    float4 bv = ((const float4*)b)[lane];
    float4 o;
    o.x = fmaxf(acc.x + bv.x, 0.0f);
    o.y = fmaxf(acc.y + bv.y, 0.0f);
    o.z = fmaxf(acc.z + bv.z, 0.0f);
    o.w = fmaxf(acc.w + bv.w, 0.0f);
    ((float4*)(out + (size_t)node * DIM))[lane] = o;
}

// ---------------------------------------------------------------------------
extern "C" void kernel_launch(void* const* d_in, const int* in_sizes, int n_in,
                              void* d_out, int out_size) {
    const float* x   = (const float*)d_in[0];
    const int*   ei  = (const int*)d_in[1];
    const float* ew  = (const float*)d_in[2];
    const float* W1  = (const float*)d_in[3];
    const float* b1  = (const float*)d_in[4];
    const float* W2  = (const float*)d_in[5];
    const float* b2  = (const float*)d_in[6];
    float* out = (float*)d_out;

    const int n = in_sizes[0] / DIM;
    const int e = in_sizes[2];
    const int* src = ei;
    const int* dst = ei + e;

    const int T = 256;
    const int gN = (n + T - 1) / T;
    const int gE = (e + T - 1) / T;
    const int nScanBlk = (n + 1023) / 1024;

    static cudaStream_t s2 = nullptr;
    static cudaEvent_t ev_fork = nullptr, ev_join = nullptr, ev_g2 = nullptr;
    static cudaEvent_t ev_c[4] = {nullptr, nullptr, nullptr, nullptr};
    static bool init_done = false;
    const int GEMM_SMEM = (DIM * WS + 2 * TM * AS) * sizeof(uint32_t);  // 200KB
    if (!init_done) {
        cudaFuncSetAttribute(k_gemm, cudaFuncAttributeMaxDynamicSharedMemorySize, GEMM_SMEM);
        cudaStreamCreateWithFlags(&s2, cudaStreamNonBlocking);
        cudaEventCreateWithFlags(&ev_fork, cudaEventDisableTiming);
        cudaEventCreateWithFlags(&ev_join, cudaEventDisableTiming);
        cudaEventCreateWithFlags(&ev_g2, cudaEventDisableTiming);
        for (int c = 0; c < 4; c++)
            cudaEventCreateWithFlags(&ev_c[c], cudaEventDisableTiming);
        init_done = true;
    }
    const int GEMM_GRID = 148;

    float* g_h_p;   cudaGetSymbolAddress((void**)&g_h_p, g_h);
    float* g_z_p;   cudaGetSymbolAddress((void**)&g_z_p, g_z);
    float* g_h2_p;  cudaGetSymbolAddress((void**)&g_h2_p, g_h2);

    // fork: CSR build on s2, GEMM-1 on main
    cudaEventRecord(ev_fork, 0);
    cudaStreamWaitEvent(s2, ev_fork, 0);

    k_init<<<gN, T, 0, s2>>>(n);                    // 0
    k_count<<<gE, T, 0, s2>>>(dst, ew, e);          // 1
    k_scan1<<<nScanBlk, 1024, 0, s2>>>(n);          // 2
    k_gemm<<<GEMM_GRID, GEMM_T, GEMM_SMEM>>>(x, W1, g_h_p, n);  // 3 <- profile target
    k_scan2<<<1, 128, 0, s2>>>(nScanBlk, n, e);     // 4
    k_scan3<<<gN, T, 0, s2>>>(n);                   // 5
    k_reorder<<<gE, T, 0, s2>>>(src, dst, ew, e);   // 6
    cudaEventRecord(ev_join, s2);
    cudaStreamWaitEvent(0, ev_join, 0);

    // layer-1 agg chunked, pipelined with layer-2 GEMM chunks on s2.
    // gemm2 writes g_h2 (NOT g_h): agg1's gather reads g_h across the full
    // node range, so g_h must stay intact until all agg1 chunks finish.
    const int NC = 4;
    const int chunk = (n + NC - 1) / NC;
    for (int c = 0; c < NC; c++) {
        int n0 = c * chunk;
        int n1 = min(n, n0 + chunk);
        int nodes = n1 - n0;
        int gWc = (nodes * 32 + T - 1) / T;
        k_agg<<<gWc, T>>>(g_h_p, b1, g_z_p, n0, n1);
        cudaEventRecord(ev_c[c], 0);
        cudaStreamWaitEvent(s2, ev_c[c], 0);
        k_gemm<<<GEMM_GRID, GEMM_T, GEMM_SMEM, s2>>>(
            g_z_p + (size_t)n0 * DIM, W2, g_h2_p + (size_t)n0 * DIM, nodes);
    }
    cudaEventRecord(ev_g2, s2);
    cudaStreamWaitEvent(0, ev_g2, 0);

    // layer 2 agg (full range), gathers from g_h2
    int gW = (n * 32 + T - 1) / T;
    k_agg<<<gW, T>>>(g_h2_p, b2, out, 0, n);
}